// round 12
// baseline (speedup 1.0000x reference)
#include <cuda_runtime.h>

#define BB 2
#define CC 64
#define DD 48
#define HH 48
#define WW 48
#define HW (HH*WW)          // 2304
#define DHW (DD*HW)         // 110592
#define TOT (BB*CC*DHW)     // 14155776

__device__ float g_t1[TOT];
__device__ float g_t2[TOT];

// ---------------------------------------------------------------------------
// Kernel 1: depthwise 5x5x5, pad 2.  x -> g_t1
// Block tile: 12z x 8y x 48w. 144 threads = 8ty x 6wg x 3zg.
// Thread: 4z x 8w outputs (depth-4 weight-row rotation). Rows as 3x LDS.128.
// Smem: 16 x 12 x 52 floats = 39.9KB (stride 52 = 13 quads, odd ->
// conflict-free) -> 5 blocks/SM (22.5 warps, occupancy lever kept with 4z).
// ---------------------------------------------------------------------------
#define S5 52
__global__ __launch_bounds__(144, 5) void dw5_kernel(
    const float* __restrict__ x,
    const float* __restrict__ w0,
    const float* __restrict__ b0)
{
    __shared__ float sh[16 * 12 * S5];   // 39936 B
    __shared__ float swp[25 * 8];        // padded (dz*5+dy)*8 + dw

    const int z0b = blockIdx.x * 12;
    const int y0  = blockIdx.y * 8;
    const int bc  = blockIdx.z;
    const int c   = bc & 63;
    const int tid = threadIdx.x;

    const float* __restrict__ xin = x + (size_t)bc * DHW;

    for (int i = tid; i < 200; i += 144) {
        int p = i >> 3, dw = i & 7;
        swp[i] = (dw < 5) ? w0[c * 125 + p * 5 + dw] : 0.f;
    }

    // Row-wise tile load: 192 rows (16 planes x 12 y).
    #pragma unroll
    for (int rr = 0; rr < 2; ++rr) {
        const int r = tid + rr * 144;
        if (r < 192) {
            const int p  = r / 12;
            const int yi = r - p * 12;
            const int gz = z0b - 2 + p;
            const int gy = y0 - 2 + yi;
            float* __restrict__ dst = &sh[r * S5];
            if ((unsigned)gz < 48u && (unsigned)gy < 48u) {
                const float4* __restrict__ src =
                    (const float4*)(xin + gz * HW + gy * WW);
                float4 q[12];
                #pragma unroll
                for (int i = 0; i < 12; ++i) q[i] = src[i];
                *(float2*)(dst) = make_float2(0.f, 0.f);
                #pragma unroll
                for (int i = 0; i < 12; ++i) {
                    *(float2*)(dst + 2 + 4 * i)     = make_float2(q[i].x, q[i].y);
                    *(float2*)(dst + 2 + 4 * i + 2) = make_float2(q[i].z, q[i].w);
                }
                *(float2*)(dst + 50) = make_float2(0.f, 0.f);
            } else {
                #pragma unroll
                for (int i = 0; i < 13; ++i)
                    *(float4*)(dst + 4 * i) = make_float4(0.f, 0.f, 0.f, 0.f);
            }
        }
    }
    __syncthreads();

    const int ty    = tid & 7;
    const int wg    = (tid >> 3) % 6;
    const int zg    = tid / 48;          // 0..2
    const int wbase = wg * 8;

    const float bias = __ldg(&b0[c]);
    float acc[4][8];
    #pragma unroll
    for (int j = 0; j < 4; ++j)
        #pragma unroll
        for (int k = 0; k < 8; ++k) acc[j][k] = bias;

    #pragma unroll 1
    for (int dy = 0; dy < 5; ++dy) {
        float wb[4][5];
        #pragma unroll
        for (int st = 0; st < 8; ++st) {
            const float4* row4 =
                (const float4*)&sh[((zg * 4 + st) * 12 + ty + dy) * S5 + wbase];
            float4 q0 = row4[0], q1 = row4[1], q2 = row4[2];
            float v[12] = {q0.x,q0.y,q0.z,q0.w, q1.x,q1.y,q1.z,q1.w,
                           q2.x,q2.y,q2.z,q2.w};

            if (st <= 4) {   // load weight row dz=st into rotation slot
                const float4 wa = *(const float4*)&swp[(st * 5 + dy) * 8];
                float* wn = wb[st & 3];
                wn[0] = wa.x; wn[1] = wa.y; wn[2] = wa.z; wn[3] = wa.w;
                wn[4] = swp[(st * 5 + dy) * 8 + 4];
            }
            #pragma unroll
            for (int j = 0; j < 4; ++j) {
                if (st - j >= 0 && st - j <= 4) {   // compile-time
                    const float* w = wb[(st - j) & 3];
                    #pragma unroll
                    for (int dw = 0; dw < 5; ++dw) {
                        const float wv = w[dw];
                        #pragma unroll
                        for (int k = 0; k < 8; ++k)
                            acc[j][k] += wv * v[k + dw];
                    }
                }
            }
        }
    }

    float* __restrict__ ob = g_t1 + (size_t)bc * DHW;
    #pragma unroll
    for (int j = 0; j < 4; ++j) {
        const int gz = z0b + zg * 4 + j;
        float4* op = (float4*)(ob + gz * HW + (y0 + ty) * WW + wbase);
        op[0] = make_float4(acc[j][0], acc[j][1], acc[j][2], acc[j][3]);
        op[1] = make_float4(acc[j][4], acc[j][5], acc[j][6], acc[j][7]);
    }
}

// ---------------------------------------------------------------------------
// Kernel 2: depthwise 7x7x7, dilation 3, pad 9.  g_t1 -> g_t2
// Residue decomposition into 27 dense 16^3 subgrids (7^3 pad-3 conv each).
// Full 16z subgrid per block; 128 threads = 16ty x 2wg x 4zg; 4z x 8w/thread.
// NEW: warp-coalesced gather (16 lanes span one row: 6 sectors vs 32) and
// smem-transposed coalesced scatter (same lane->w mapping on store side).
// Smem (dynamic 55776B): swp[392] + sh[22 x 22 x 28].
// ---------------------------------------------------------------------------
#define S7 28
__global__ __launch_bounds__(128) void dw7_kernel(
    const float* __restrict__ ws,
    const float* __restrict__ bs)
{
    extern __shared__ float dsm[];
    float* __restrict__ swp = dsm;          // 392 floats
    float* __restrict__ sh  = dsm + 392;    // 22*22*28 = 13552 floats

    const int res = blockIdx.x;          // 0..26
    const int rz = res / 9, ry = (res / 3) % 3, rw = res % 3;
    const int c  = blockIdx.y;
    const int b  = blockIdx.z;
    const int bc = b * 64 + c;
    const int tid = threadIdx.x;

    const float* __restrict__ xin = g_t1 + (size_t)bc * DHW;

    for (int i = tid; i < 392; i += 128) {
        int p = i >> 3, dw = i & 7;
        swp[i] = (dw < 7) ? ws[c * 343 + p * 7 + dw] : 0.f;
    }

    // Zero-fill tile (halo + padding), then coalesced data gather.
    for (int i = tid; i < (22 * 22 * S7) / 4; i += 128)
        ((float4*)sh)[i] = make_float4(0.f, 0.f, 0.f, 0.f);
    __syncthreads();

    {
        const int lw  = tid & 15;        // w-index within row
        const int lr  = (tid >> 4) & 1;  // row parity within warp
        const int wrp = tid >> 5;        // warp 0..3
        #pragma unroll 4
        for (int it = 0; it < 61; ++it) {
            const int r = it * 8 + wrp * 2 + lr;   // 0..487
            if (r < 484) {
                const int p  = r / 22;
                const int yi = r - p * 22;
                const int sz = p - 3, sy = yi - 3;
                if ((unsigned)sz < 16u && (unsigned)sy < 16u) {
                    sh[r * S7 + 3 + lw] =
                        xin[(3 * sz + rz) * HW + (3 * sy + ry) * WW + rw + 3 * lw];
                }
            }
        }
    }
    __syncthreads();

    const int ty    = tid & 15;
    const int wg    = (tid >> 4) & 1;
    const int zg    = tid >> 5;          // 0..3
    const int wbase = wg * 8;

    const float bias = __ldg(&bs[c]);
    float acc[4][8];
    #pragma unroll
    for (int j = 0; j < 4; ++j)
        #pragma unroll
        for (int k = 0; k < 8; ++k) acc[j][k] = bias;

    #pragma unroll 1
    for (int dy = 0; dy < 7; ++dy) {
        float wb[4][7];
        #pragma unroll
        for (int st = 0; st < 10; ++st) {
            const float4* row4 =
                (const float4*)&sh[((zg * 4 + st) * 22 + ty + dy) * S7 + wbase];
            float4 q0 = row4[0], q1 = row4[1], q2 = row4[2], q3 = row4[3];
            float v[16] = {q0.x,q0.y,q0.z,q0.w, q1.x,q1.y,q1.z,q1.w,
                           q2.x,q2.y,q2.z,q2.w, q3.x,q3.y,q3.z,q3.w};

            if (st <= 6) {   // load weight row dz=st into rotation slot
                const float4* wq = (const float4*)&swp[(st * 7 + dy) * 8];
                const float4 wa = wq[0], wc = wq[1];
                float* wn = wb[st & 3];
                wn[0] = wa.x; wn[1] = wa.y; wn[2] = wa.z; wn[3] = wa.w;
                wn[4] = wc.x; wn[5] = wc.y; wn[6] = wc.z;
            }
            #pragma unroll
            for (int j = 0; j < 4; ++j) {
                if (st - j >= 0 && st - j <= 6) {   // compile-time
                    const float* w = wb[(st - j) & 3];
                    #pragma unroll
                    for (int dw = 0; dw < 7; ++dw) {
                        const float wv = w[dw];
                        #pragma unroll
                        for (int k = 0; k < 8; ++k)
                            acc[j][k] += wv * v[k + dw];
                    }
                }
            }
        }
    }

    // Coalesced scatter: transpose accs through smem (subgrid [sz][sy][w],
    // row stride 17 -> conflict-free STS), then lane->w cooperative STG.
    __syncthreads();     // all tile reads done; safe to overwrite sh
    #pragma unroll
    for (int j = 0; j < 4; ++j) {
        const int sz = zg * 4 + j;
        float* srow = &sh[(sz * 16 + ty) * 17 + wbase];
        #pragma unroll
        for (int k = 0; k < 8; ++k) srow[k] = acc[j][k];
    }
    __syncthreads();
    {
        const int lw  = tid & 15;
        const int lr  = (tid >> 4) & 1;
        const int wrp = tid >> 5;
        float* __restrict__ ob = g_t2 + (size_t)bc * DHW;
        #pragma unroll 4
        for (int it = 0; it < 32; ++it) {
            const int q  = it * 8 + wrp * 2 + lr;  // 0..255
            const int sz = q >> 4, sy = q & 15;
            const float val = sh[q * 17 + lw];
            ob[(3 * sz + rz) * HW + (3 * sy + ry) * WW + rw + 3 * lw] = val;
        }
    }
}

#define DW7_SMEM ((392 + 22 * 22 * S7) * 4)   // 55776 B

// ---------------------------------------------------------------------------
// Kernel 3: pointwise 64x64 conv + bias + gate by x.  g_t2, x -> out
// Block: 128 points x 64 co. 128 threads = 16 pg (8 pts) x 8 cg (8 co).
// Per ci: 2 LDG.128 (t2, L1 reuse) + 2 broadcast LDS.128 (8 co wt) + 64 FFMA.
// ---------------------------------------------------------------------------
__global__ __launch_bounds__(128) void pw_kernel(
    const float* __restrict__ x,
    const float* __restrict__ w1,
    const float* __restrict__ b1,
    float* __restrict__ out)
{
    __shared__ float sWt[64 * 64];       // [ci][co]

    const int p0  = blockIdx.x * 128;
    const int b   = blockIdx.y;
    const int tid = threadIdx.x;

    for (int i = tid; i < 4096; i += 128) {
        int co = i >> 6, ci = i & 63;
        sWt[ci * 64 + co] = w1[i];
    }
    __syncthreads();

    const int pg = tid & 15;      // 16 groups of 8 points
    const int cg = tid >> 4;      // 8 groups of 8 out-channels

    float acc[8][8];
    #pragma unroll
    for (int j = 0; j < 8; ++j) {
        const float bias = __ldg(&b1[cg * 8 + j]);
        #pragma unroll
        for (int k = 0; k < 8; ++k) acc[j][k] = bias;
    }

    const float4* __restrict__ tp =
        (const float4*)(g_t2 + (size_t)b * 64 * DHW + p0) + pg * 2;

    #pragma unroll 2
    for (int ci = 0; ci < 64; ++ci) {
        const float4 A = __ldg(tp + (size_t)ci * (DHW / 4));
        const float4 B = __ldg(tp + (size_t)ci * (DHW / 4) + 1);
        const float4* wq = (const float4*)&sWt[ci * 64 + cg * 8];
        const float4 w0v = wq[0], w1v = wq[1];
        const float w8[8] = {w0v.x, w0v.y, w0v.z, w0v.w,
                             w1v.x, w1v.y, w1v.z, w1v.w};
        #pragma unroll
        for (int j = 0; j < 8; ++j) {
            const float w = w8[j];
            acc[j][0] += w * A.x;  acc[j][1] += w * A.y;
            acc[j][2] += w * A.z;  acc[j][3] += w * A.w;
            acc[j][4] += w * B.x;  acc[j][5] += w * B.y;
            acc[j][6] += w * B.z;  acc[j][7] += w * B.w;
        }
    }

    #pragma unroll
    for (int j = 0; j < 8; ++j) {
        const int co = cg * 8 + j;
        const size_t off = (size_t)(b * 64 + co) * DHW + p0 + pg * 8;
        const float4 xa = __ldg((const float4*)(x + off));
        const float4 xb = __ldg((const float4*)(x + off + 4));
        float4 o0 = make_float4(xa.x * acc[j][0], xa.y * acc[j][1],
                                xa.z * acc[j][2], xa.w * acc[j][3]);
        float4 o1 = make_float4(xb.x * acc[j][4], xb.y * acc[j][5],
                                xb.z * acc[j][6], xb.w * acc[j][7]);
        *(float4*)(out + off)     = o0;
        *(float4*)(out + off + 4) = o1;
    }
}

// ---------------------------------------------------------------------------
extern "C" void kernel_launch(void* const* d_in, const int* in_sizes, int n_in,
                              void* d_out, int out_size)
{
    const float* x  = (const float*)d_in[0];
    const float* w0 = (const float*)d_in[1];
    const float* b0 = (const float*)d_in[2];
    const float* ws = (const float*)d_in[3];
    const float* bs = (const float*)d_in[4];
    const float* w1 = (const float*)d_in[5];
    const float* b1 = (const float*)d_in[6];
    float* out = (float*)d_out;

    // Metadata-only, capture-legal, no allocation (proven safe R9/R11).
    cudaFuncSetAttribute(dw7_kernel,
                         cudaFuncAttributeMaxDynamicSharedMemorySize, DW7_SMEM);

    dw5_kernel<<<dim3(4, 6, BB * CC), 144>>>(x, w0, b0);
    dw7_kernel<<<dim3(27, CC, BB), 128, DW7_SMEM>>>(ws, bs);
    pw_kernel<<<dim3(DHW / 128, BB), 128>>>(x, w1, b1, out);
}

// round 13
// speedup vs baseline: 1.1002x; 1.1002x over previous
#include <cuda_runtime.h>

#define BB 2
#define CC 64
#define DD 48
#define HH 48
#define WW 48
#define HW (HH*WW)          // 2304
#define DHW (DD*HW)         // 110592
#define TOT (BB*CC*DHW)     // 14155776

__device__ float g_t1[TOT];
__device__ float g_t2[TOT];

// ---------------------------------------------------------------------------
// Kernel 1: depthwise 5x5x5, pad 2.  x -> g_t1   (round-12 best: 95.5us)
// Block tile: 12z x 8y x 48w. 144 threads = 8ty x 6wg x 3zg.
// Thread: 4z x 8w outputs (depth-4 weight-row rotation). Rows as 3x LDS.128.
// Smem: 16 x 12 x 52 floats = 39.9KB -> 5 blocks/SM.
// ---------------------------------------------------------------------------
#define S5 52
__global__ __launch_bounds__(144, 5) void dw5_kernel(
    const float* __restrict__ x,
    const float* __restrict__ w0,
    const float* __restrict__ b0)
{
    __shared__ float sh[16 * 12 * S5];   // 39936 B
    __shared__ float swp[25 * 8];        // padded (dz*5+dy)*8 + dw

    const int z0b = blockIdx.x * 12;
    const int y0  = blockIdx.y * 8;
    const int bc  = blockIdx.z;
    const int c   = bc & 63;
    const int tid = threadIdx.x;

    const float* __restrict__ xin = x + (size_t)bc * DHW;

    for (int i = tid; i < 200; i += 144) {
        int p = i >> 3, dw = i & 7;
        swp[i] = (dw < 5) ? w0[c * 125 + p * 5 + dw] : 0.f;
    }

    // Row-wise tile load: 192 rows (16 planes x 12 y).
    #pragma unroll
    for (int rr = 0; rr < 2; ++rr) {
        const int r = tid + rr * 144;
        if (r < 192) {
            const int p  = r / 12;
            const int yi = r - p * 12;
            const int gz = z0b - 2 + p;
            const int gy = y0 - 2 + yi;
            float* __restrict__ dst = &sh[r * S5];
            if ((unsigned)gz < 48u && (unsigned)gy < 48u) {
                const float4* __restrict__ src =
                    (const float4*)(xin + gz * HW + gy * WW);
                float4 q[12];
                #pragma unroll
                for (int i = 0; i < 12; ++i) q[i] = src[i];
                *(float2*)(dst) = make_float2(0.f, 0.f);
                #pragma unroll
                for (int i = 0; i < 12; ++i) {
                    *(float2*)(dst + 2 + 4 * i)     = make_float2(q[i].x, q[i].y);
                    *(float2*)(dst + 2 + 4 * i + 2) = make_float2(q[i].z, q[i].w);
                }
                *(float2*)(dst + 50) = make_float2(0.f, 0.f);
            } else {
                #pragma unroll
                for (int i = 0; i < 13; ++i)
                    *(float4*)(dst + 4 * i) = make_float4(0.f, 0.f, 0.f, 0.f);
            }
        }
    }
    __syncthreads();

    const int ty    = tid & 7;
    const int wg    = (tid >> 3) % 6;
    const int zg    = tid / 48;          // 0..2
    const int wbase = wg * 8;

    const float bias = __ldg(&b0[c]);
    float acc[4][8];
    #pragma unroll
    for (int j = 0; j < 4; ++j)
        #pragma unroll
        for (int k = 0; k < 8; ++k) acc[j][k] = bias;

    #pragma unroll 1
    for (int dy = 0; dy < 5; ++dy) {
        float wb[4][5];
        #pragma unroll
        for (int st = 0; st < 8; ++st) {
            const float4* row4 =
                (const float4*)&sh[((zg * 4 + st) * 12 + ty + dy) * S5 + wbase];
            float4 q0 = row4[0], q1 = row4[1], q2 = row4[2];
            float v[12] = {q0.x,q0.y,q0.z,q0.w, q1.x,q1.y,q1.z,q1.w,
                           q2.x,q2.y,q2.z,q2.w};

            if (st <= 4) {   // load weight row dz=st into rotation slot
                const float4 wa = *(const float4*)&swp[(st * 5 + dy) * 8];
                float* wn = wb[st & 3];
                wn[0] = wa.x; wn[1] = wa.y; wn[2] = wa.z; wn[3] = wa.w;
                wn[4] = swp[(st * 5 + dy) * 8 + 4];
            }
            #pragma unroll
            for (int j = 0; j < 4; ++j) {
                if (st - j >= 0 && st - j <= 4) {   // compile-time
                    const float* w = wb[(st - j) & 3];
                    #pragma unroll
                    for (int dw = 0; dw < 5; ++dw) {
                        const float wv = w[dw];
                        #pragma unroll
                        for (int k = 0; k < 8; ++k)
                            acc[j][k] += wv * v[k + dw];
                    }
                }
            }
        }
    }

    float* __restrict__ ob = g_t1 + (size_t)bc * DHW;
    #pragma unroll
    for (int j = 0; j < 4; ++j) {
        const int gz = z0b + zg * 4 + j;
        float4* op = (float4*)(ob + gz * HW + (y0 + ty) * WW + wbase);
        op[0] = make_float4(acc[j][0], acc[j][1], acc[j][2], acc[j][3]);
        op[1] = make_float4(acc[j][4], acc[j][5], acc[j][6], acc[j][7]);
    }
}

// ---------------------------------------------------------------------------
// Kernel 2: depthwise 7x7x7, dilation 3, pad 9.  g_t1 -> g_t2
// ROUND-11 VERSION VERBATIM (best measured dw7; R12 restructure regressed).
// Residue decomposition into 27 dense 16^3 subgrids (7^3 pad-3 conv each).
// Full 16z subgrid per block. 128 threads = 16ty x 2wg x 4zg; 4z x 8w/thread
// with depth-4 weight rotation. Smem (dynamic 55776B).
// ---------------------------------------------------------------------------
#define S7 28
__global__ __launch_bounds__(128) void dw7_kernel(
    const float* __restrict__ ws,
    const float* __restrict__ bs)
{
    extern __shared__ float dsm[];
    float* __restrict__ swp = dsm;          // 392 floats
    float* __restrict__ sh  = dsm + 392;    // 22*22*28 = 13552 floats

    const int res = blockIdx.x;          // 0..26
    const int rz = res / 9, ry = (res / 3) % 3, rw = res % 3;
    const int c  = blockIdx.y;
    const int b  = blockIdx.z;
    const int bc = b * 64 + c;
    const int tid = threadIdx.x;

    const float* __restrict__ xin = g_t1 + (size_t)bc * DHW;

    for (int i = tid; i < 392; i += 128) {
        int p = i >> 3, dw = i & 7;
        swp[i] = (dw < 7) ? ws[c * 343 + p * 7 + dw] : 0.f;
    }

    // Row-wise tile load: 484 rows (22 planes x 22 y), 128 threads.
    #pragma unroll
    for (int rr = 0; rr < 4; ++rr) {
        const int r = tid + rr * 128;
        if (r < 484) {
            const int p  = r / 22;           // plane 0..21
            const int yi = r - p * 22;       // 0..21
            const int sz = p - 3;            // subgrid z of this plane
            const int sy = yi - 3;
            float* __restrict__ dst = &sh[r * S7];
            if ((unsigned)sz < 16u && (unsigned)sy < 16u) {
                const float* __restrict__ src =
                    xin + (3 * sz + rz) * HW + (3 * sy + ry) * WW + rw;
                float d[16];
                #pragma unroll
                for (int j = 0; j < 16; ++j) d[j] = src[3 * j];
                float4* __restrict__ dq = (float4*)dst;
                dq[0] = make_float4(0.f, 0.f, 0.f, d[0]);
                dq[1] = make_float4(d[1], d[2], d[3], d[4]);
                dq[2] = make_float4(d[5], d[6], d[7], d[8]);
                dq[3] = make_float4(d[9], d[10], d[11], d[12]);
                dq[4] = make_float4(d[13], d[14], d[15], 0.f);
                dq[5] = make_float4(0.f, 0.f, 0.f, 0.f);
                dq[6] = make_float4(0.f, 0.f, 0.f, 0.f);
            } else {
                float4* __restrict__ dq = (float4*)dst;
                #pragma unroll
                for (int i = 0; i < 7; ++i)
                    dq[i] = make_float4(0.f, 0.f, 0.f, 0.f);
            }
        }
    }
    __syncthreads();

    const int ty    = tid & 15;
    const int wg    = (tid >> 4) & 1;
    const int zg    = tid >> 5;          // 0..3
    const int wbase = wg * 8;

    const float bias = __ldg(&bs[c]);
    float acc[4][8];
    #pragma unroll
    for (int j = 0; j < 4; ++j)
        #pragma unroll
        for (int k = 0; k < 8; ++k) acc[j][k] = bias;

    #pragma unroll 1
    for (int dy = 0; dy < 7; ++dy) {
        float wb[4][7];
        #pragma unroll
        for (int st = 0; st < 10; ++st) {
            const float4* row4 =
                (const float4*)&sh[((zg * 4 + st) * 22 + ty + dy) * S7 + wbase];
            float4 q0 = row4[0], q1 = row4[1], q2 = row4[2], q3 = row4[3];
            float v[16] = {q0.x,q0.y,q0.z,q0.w, q1.x,q1.y,q1.z,q1.w,
                           q2.x,q2.y,q2.z,q2.w, q3.x,q3.y,q3.z,q3.w};

            if (st <= 6) {   // load weight row dz=st into rotation slot
                const float4* wq = (const float4*)&swp[(st * 7 + dy) * 8];
                const float4 wa = wq[0], wc = wq[1];
                float* wn = wb[st & 3];
                wn[0] = wa.x; wn[1] = wa.y; wn[2] = wa.z; wn[3] = wa.w;
                wn[4] = wc.x; wn[5] = wc.y; wn[6] = wc.z;
            }
            #pragma unroll
            for (int j = 0; j < 4; ++j) {
                if (st - j >= 0 && st - j <= 6) {   // compile-time
                    const float* w = wb[(st - j) & 3];
                    #pragma unroll
                    for (int dw = 0; dw < 7; ++dw) {
                        const float wv = w[dw];
                        #pragma unroll
                        for (int k = 0; k < 8; ++k)
                            acc[j][k] += wv * v[k + dw];
                    }
                }
            }
        }
    }

    float* __restrict__ ob = g_t2 + (size_t)bc * DHW;
    #pragma unroll
    for (int j = 0; j < 4; ++j) {
        const int sz = zg * 4 + j;            // 0..15
        const int gz = 3 * sz + rz;
        const int gy = 3 * ty + ry;
        float* op = ob + gz * HW + gy * WW + rw;
        #pragma unroll
        for (int k = 0; k < 8; ++k)
            op[3 * (wbase + k)] = acc[j][k];
    }
}

#define DW7_SMEM ((392 + 22 * 22 * S7) * 4)   // 55776 B

// ---------------------------------------------------------------------------
// Kernel 3: pointwise 64x64 conv + bias + gate by x.  g_t2, x -> out
// Block: 128 points x 64 co. 128 threads = 16 pg (8 pts) x 8 cg (8 co).
// Per ci: 2 LDG.128 (t2, L1 reuse) + 2 broadcast LDS.128 (8 co wt) + 64 FFMA.
// ---------------------------------------------------------------------------
__global__ __launch_bounds__(128) void pw_kernel(
    const float* __restrict__ x,
    const float* __restrict__ w1,
    const float* __restrict__ b1,
    float* __restrict__ out)
{
    __shared__ float sWt[64 * 64];       // [ci][co]

    const int p0  = blockIdx.x * 128;
    const int b   = blockIdx.y;
    const int tid = threadIdx.x;

    for (int i = tid; i < 4096; i += 128) {
        int co = i >> 6, ci = i & 63;
        sWt[ci * 64 + co] = w1[i];
    }
    __syncthreads();

    const int pg = tid & 15;      // 16 groups of 8 points
    const int cg = tid >> 4;      // 8 groups of 8 out-channels

    float acc[8][8];
    #pragma unroll
    for (int j = 0; j < 8; ++j) {
        const float bias = __ldg(&b1[cg * 8 + j]);
        #pragma unroll
        for (int k = 0; k < 8; ++k) acc[j][k] = bias;
    }

    const float4* __restrict__ tp =
        (const float4*)(g_t2 + (size_t)b * 64 * DHW + p0) + pg * 2;

    #pragma unroll 2
    for (int ci = 0; ci < 64; ++ci) {
        const float4 A = __ldg(tp + (size_t)ci * (DHW / 4));
        const float4 B = __ldg(tp + (size_t)ci * (DHW / 4) + 1);
        const float4* wq = (const float4*)&sWt[ci * 64 + cg * 8];
        const float4 w0v = wq[0], w1v = wq[1];
        const float w8[8] = {w0v.x, w0v.y, w0v.z, w0v.w,
                             w1v.x, w1v.y, w1v.z, w1v.w};
        #pragma unroll
        for (int j = 0; j < 8; ++j) {
            const float w = w8[j];
            acc[j][0] += w * A.x;  acc[j][1] += w * A.y;
            acc[j][2] += w * A.z;  acc[j][3] += w * A.w;
            acc[j][4] += w * B.x;  acc[j][5] += w * B.y;
            acc[j][6] += w * B.z;  acc[j][7] += w * B.w;
        }
    }

    #pragma unroll
    for (int j = 0; j < 8; ++j) {
        const int co = cg * 8 + j;
        const size_t off = (size_t)(b * 64 + co) * DHW + p0 + pg * 8;
        const float4 xa = __ldg((const float4*)(x + off));
        const float4 xb = __ldg((const float4*)(x + off + 4));
        float4 o0 = make_float4(xa.x * acc[j][0], xa.y * acc[j][1],
                                xa.z * acc[j][2], xa.w * acc[j][3]);
        float4 o1 = make_float4(xb.x * acc[j][4], xb.y * acc[j][5],
                                xb.z * acc[j][6], xb.w * acc[j][7]);
        *(float4*)(out + off)     = o0;
        *(float4*)(out + off + 4) = o1;
    }
}

// ---------------------------------------------------------------------------
extern "C" void kernel_launch(void* const* d_in, const int* in_sizes, int n_in,
                              void* d_out, int out_size)
{
    const float* x  = (const float*)d_in[0];
    const float* w0 = (const float*)d_in[1];
    const float* b0 = (const float*)d_in[2];
    const float* ws = (const float*)d_in[3];
    const float* bs = (const float*)d_in[4];
    const float* w1 = (const float*)d_in[5];
    const float* b1 = (const float*)d_in[6];
    float* out = (float*)d_out;

    // Metadata-only, capture-legal, no allocation (proven safe R9/R11/R12).
    cudaFuncSetAttribute(dw7_kernel,
                         cudaFuncAttributeMaxDynamicSharedMemorySize, DW7_SMEM);

    dw5_kernel<<<dim3(4, 6, BB * CC), 144>>>(x, w0, b0);
    dw7_kernel<<<dim3(27, CC, BB), 128, DW7_SMEM>>>(ws, bs);
    pw_kernel<<<dim3(DHW / 128, BB), 128>>>(x, w1, b1, out);
}